// round 1
// baseline (speedup 1.0000x reference)
#include <cuda_runtime.h>
#include <mma.h>

using namespace nvcuda;

// Problem dims
constexpr int Bn  = 8;
constexpr int Sn  = 2048;
constexpr int Dn  = 512;
constexpr int Hn  = 8;
constexpr int LATn = 64;
constexpr int OUTn = 64;

// Device-global scratch (no allocation allowed in kernel_launch)
__device__ float g_Q[Bn * Hn * Sn * LATn];   // [b,h,s,lat]
__device__ float g_K[Bn * Hn * Sn * LATn];   // [b,h,s,lat]
__device__ float g_V[Bn * Hn * Sn * OUTn];   // [b,h,s,out]
__device__ float g_O[Bn * Sn * Hn * OUTn];   // [b,s,h*out]  (concat heads)

// ---------------------------------------------------------------------------
// Shared 64x64 output-tile GEMM, K=512, TF32 wmma (m16n16k8).
// A: row-major [64+, 512] with leading dim lda (rows start at A)
// Bm: row-major [512, 64]
// C: row-major, leading dim ldc
// Block: 256 threads = 8 warps; warp w computes a 16x32 sub-tile.
// ---------------------------------------------------------------------------
__device__ __forceinline__ void gemm64x64_k512(
    const float* __restrict__ A, int lda,
    const float* __restrict__ Bm,
    float* __restrict__ C, int ldc)
{
    __shared__ __align__(16) float As[64 * 32];
    __shared__ __align__(16) float Bs[32 * 64];

    const int tid = threadIdx.x;
    const int w   = tid >> 5;
    const int tr  = w >> 1;           // 0..3  (16-row tile index)
    const int tc0 = (w & 1) * 2;      // 0 or 2 (first 16-col tile index)

    wmma::fragment<wmma::accumulator, 16, 16, 8, float> acc0, acc1;
    wmma::fill_fragment(acc0, 0.0f);
    wmma::fill_fragment(acc1, 0.0f);

    for (int kc = 0; kc < 512; kc += 32) {
        __syncthreads();
#pragma unroll
        for (int i = 0; i < 8; i++) {
            int idx = tid + i * 256;
            As[idx] = A[(idx >> 5) * lda + kc + (idx & 31)];
            Bs[idx] = Bm[(kc + (idx >> 6)) * 64 + (idx & 63)];
        }
        __syncthreads();
#pragma unroll
        for (int ks = 0; ks < 4; ks++) {
            wmma::fragment<wmma::matrix_a, 16, 16, 8, wmma::precision::tf32, wmma::row_major> af;
            wmma::fragment<wmma::matrix_b, 16, 16, 8, wmma::precision::tf32, wmma::row_major> bf0, bf1;
            wmma::load_matrix_sync(af,  As + tr * 16 * 32 + ks * 8, 32);
            wmma::load_matrix_sync(bf0, Bs + ks * 8 * 64 + tc0 * 16, 64);
            wmma::load_matrix_sync(bf1, Bs + ks * 8 * 64 + (tc0 + 1) * 16, 64);
#pragma unroll
            for (int t = 0; t < af.num_elements; t++)
                af.x[t] = wmma::__float_to_tf32(af.x[t]);
#pragma unroll
            for (int t = 0; t < bf0.num_elements; t++) {
                bf0.x[t] = wmma::__float_to_tf32(bf0.x[t]);
                bf1.x[t] = wmma::__float_to_tf32(bf1.x[t]);
            }
            wmma::mma_sync(acc0, af, bf0, acc0);
            wmma::mma_sync(acc1, af, bf1, acc1);
        }
    }
    wmma::store_matrix_sync(C + tr * 16 * ldc + tc0 * 16,       acc0, ldc, wmma::mem_row_major);
    wmma::store_matrix_sync(C + tr * 16 * ldc + (tc0 + 1) * 16, acc1, ldc, wmma::mem_row_major);
}

// ---------------------------------------------------------------------------
// Kernel 1: QKV projections. grid = (S/64, B, 3*H)
// ---------------------------------------------------------------------------
__global__ void proj_kernel(const float* __restrict__ x,
                            const float* __restrict__ WQ,
                            const float* __restrict__ WK,
                            const float* __restrict__ WV)
{
    const int s0    = blockIdx.x * 64;
    const int b     = blockIdx.y;
    const int z     = blockIdx.z;
    const int h     = z & 7;
    const int which = z >> 3;  // 0=Q 1=K 2=V

    const float* W  = (which == 0) ? WQ : (which == 1) ? WK : WV;
    float*       Og = (which == 0) ? g_Q : (which == 1) ? g_K : g_V;

    const float* A  = x + (b * Sn + s0) * Dn;
    const float* Bm = W + h * Dn * 64;
    float*       C  = Og + ((b * Hn + h) * Sn + s0) * 64;

    gemm64x64_k512(A, Dn, Bm, C, 64);
}

// ---------------------------------------------------------------------------
// Kernel 2: flash attention. grid = (S/64, H, B), 256 threads.
// Dynamic smem: Qs(64x64) Ks(64x64) Vs(64x64) Os(64x64) Ss(64x72)
// ---------------------------------------------------------------------------
__global__ void flash_kernel()
{
    extern __shared__ __align__(16) float sm[];
    float* Qs = sm;             // 4096 floats
    float* Ks = sm + 4096;      // 4096
    float* Vs = sm + 8192;      // 4096
    float* Os = sm + 12288;     // 4096
    float* Ss = sm + 16384;     // 64*72 = 4608 floats (padded ld=72)

    const int tid  = threadIdx.x;
    const int w    = tid >> 5;
    const int lane = tid & 31;
    const int b    = blockIdx.z;
    const int h    = blockIdx.y;
    const int q0   = blockIdx.x * 64;

    const float* Qg = g_Q + ((b * Hn + h) * Sn + q0) * 64;
    const float* Kg = g_K + (b * Hn + h) * Sn * 64;
    const float* Vg = g_V + (b * Hn + h) * Sn * 64;

    // Load Q tile; zero O accumulator
    for (int i = tid; i < 4096; i += 256) {
        Qs[i] = Qg[i];
        Os[i] = 0.0f;
    }

    // Softmax row mapping: warp w owns rows 8w..8w+7; quad of 4 lanes per row,
    // each lane covers 16 columns.
    const int row = w * 8 + (lane >> 2);
    const int c0  = (lane & 3) * 16;
    float m_r = -1e30f;
    float l_r = 0.0f;

    // wmma tile mapping (same as gemm): warp w -> 16 rows x 32 cols
    const int tr  = w >> 1;
    const int tc0 = (w & 1) * 2;

    const float scale = 0.125f;  // 1/sqrt(64)

    for (int j = 0; j < Sn; j += 64) {
        __syncthreads();  // prior iteration's reads of Ks/Vs/Ss/Os complete

        // Load K and V tiles (float4 vectorized; 4096 floats each)
        const float4* K4  = (const float4*)(Kg + j * 64);
        const float4* V4  = (const float4*)(Vg + j * 64);
        float4*       Ks4 = (float4*)Ks;
        float4*       Vs4 = (float4*)Vs;
#pragma unroll
        for (int i = 0; i < 4; i++) {
            Ks4[tid + i * 256] = K4[tid + i * 256];
            Vs4[tid + i * 256] = V4[tid + i * 256];
        }
        __syncthreads();

        // ---- S = Q @ K^T  (64x64x64) ----
        wmma::fragment<wmma::accumulator, 16, 16, 8, float> sa0, sa1;
        wmma::fill_fragment(sa0, 0.0f);
        wmma::fill_fragment(sa1, 0.0f);
#pragma unroll
        for (int ks = 0; ks < 8; ks++) {
            wmma::fragment<wmma::matrix_a, 16, 16, 8, wmma::precision::tf32, wmma::row_major> af;
            wmma::fragment<wmma::matrix_b, 16, 16, 8, wmma::precision::tf32, wmma::col_major> bf0, bf1;
            wmma::load_matrix_sync(af,  Qs + tr * 16 * 64 + ks * 8, 64);
            // K^T: element (k, n) lives at Ks[n*64 + k] -> col_major, ldm=64
            wmma::load_matrix_sync(bf0, Ks + (tc0 * 16) * 64 + ks * 8, 64);
            wmma::load_matrix_sync(bf1, Ks + ((tc0 + 1) * 16) * 64 + ks * 8, 64);
#pragma unroll
            for (int t = 0; t < af.num_elements; t++)
                af.x[t] = wmma::__float_to_tf32(af.x[t]);
#pragma unroll
            for (int t = 0; t < bf0.num_elements; t++) {
                bf0.x[t] = wmma::__float_to_tf32(bf0.x[t]);
                bf1.x[t] = wmma::__float_to_tf32(bf1.x[t]);
            }
            wmma::mma_sync(sa0, af, bf0, sa0);
            wmma::mma_sync(sa1, af, bf1, sa1);
        }
        wmma::store_matrix_sync(Ss + tr * 16 * 72 + tc0 * 16,       sa0, 72, wmma::mem_row_major);
        wmma::store_matrix_sync(Ss + tr * 16 * 72 + (tc0 + 1) * 16, sa1, 72, wmma::mem_row_major);
        __syncthreads();

        // ---- online softmax on Ss rows; prescale Os by alpha ----
        float vals[16];
        float mloc = -1e30f;
#pragma unroll
        for (int c = 0; c < 16; c++) {
            float v = Ss[row * 72 + c0 + c] * scale;
            vals[c] = v;
            mloc = fmaxf(mloc, v);
        }
        mloc = fmaxf(mloc, __shfl_xor_sync(0xffffffffu, mloc, 1));
        mloc = fmaxf(mloc, __shfl_xor_sync(0xffffffffu, mloc, 2));
        const float m_new = fmaxf(m_r, mloc);
        const float alpha = __expf(m_r - m_new);

        float psum = 0.0f;
#pragma unroll
        for (int c = 0; c < 16; c++) {
            float p = __expf(vals[c] - m_new);
            Ss[row * 72 + c0 + c] = p;
            psum += p;
        }
        psum += __shfl_xor_sync(0xffffffffu, psum, 1);
        psum += __shfl_xor_sync(0xffffffffu, psum, 2);
        l_r = l_r * alpha + psum;
        m_r = m_new;

#pragma unroll
        for (int c = 0; c < 16; c++)
            Os[row * 64 + c0 + c] *= alpha;
        __syncthreads();

        // ---- O += P @ V  (64x64x64), accumulate into Os via wmma c-frag ----
        wmma::fragment<wmma::accumulator, 16, 16, 8, float> oa0, oa1;
        wmma::load_matrix_sync(oa0, Os + tr * 16 * 64 + tc0 * 16,       64, wmma::mem_row_major);
        wmma::load_matrix_sync(oa1, Os + tr * 16 * 64 + (tc0 + 1) * 16, 64, wmma::mem_row_major);
#pragma unroll
        for (int ks = 0; ks < 8; ks++) {
            wmma::fragment<wmma::matrix_a, 16, 16, 8, wmma::precision::tf32, wmma::row_major> af;
            wmma::fragment<wmma::matrix_b, 16, 16, 8, wmma::precision::tf32, wmma::row_major> bf0, bf1;
            wmma::load_matrix_sync(af,  Ss + tr * 16 * 72 + ks * 8, 72);
            wmma::load_matrix_sync(bf0, Vs + ks * 8 * 64 + tc0 * 16, 64);
            wmma::load_matrix_sync(bf1, Vs + ks * 8 * 64 + (tc0 + 1) * 16, 64);
#pragma unroll
            for (int t = 0; t < af.num_elements; t++)
                af.x[t] = wmma::__float_to_tf32(af.x[t]);
#pragma unroll
            for (int t = 0; t < bf0.num_elements; t++) {
                bf0.x[t] = wmma::__float_to_tf32(bf0.x[t]);
                bf1.x[t] = wmma::__float_to_tf32(bf1.x[t]);
            }
            wmma::mma_sync(oa0, af, bf0, oa0);
            wmma::mma_sync(oa1, af, bf1, oa1);
        }
        wmma::store_matrix_sync(Os + tr * 16 * 64 + tc0 * 16,       oa0, 64, wmma::mem_row_major);
        wmma::store_matrix_sync(Os + tr * 16 * 64 + (tc0 + 1) * 16, oa1, 64, wmma::mem_row_major);
    }
    __syncthreads();

    // Finalize: divide by l, write to concat buffer g_O[b, s, h*64 + c]
    const float inv_l = 1.0f / l_r;
    float* Og = g_O + (size_t)(b * Sn + q0 + row) * (Hn * OUTn) + h * 64 + c0;
#pragma unroll
    for (int c = 0; c < 16; c++)
        Og[c] = Os[row * 64 + c0 + c] * inv_l;
}

// ---------------------------------------------------------------------------
// Kernel 3: output projection. grid = (B*S/64)
// ---------------------------------------------------------------------------
__global__ void oproj_kernel(const float* __restrict__ WO, float* __restrict__ out)
{
    const int r0 = blockIdx.x * 64;
    gemm64x64_k512(g_O + (size_t)r0 * 512, 512, WO, out + (size_t)r0 * 64, 64);
}

// ---------------------------------------------------------------------------
extern "C" void kernel_launch(void* const* d_in, const int* in_sizes, int n_in,
                              void* d_out, int out_size)
{
    const float* x  = (const float*)d_in[0];
    const float* WQ = (const float*)d_in[1];
    const float* WK = (const float*)d_in[2];
    const float* WV = (const float*)d_in[3];
    const float* WO = (const float*)d_in[4];
    float* out = (float*)d_out;

    // QKV projections
    proj_kernel<<<dim3(Sn / 64, Bn, 3 * Hn), 256>>>(x, WQ, WK, WV);

    // Flash attention (84 KB dynamic smem -> opt-in)
    constexpr int FLASH_SMEM = (4096 * 4 + 64 * 72) * (int)sizeof(float);  // 83968 B
    cudaFuncSetAttribute(flash_kernel, cudaFuncAttributeMaxDynamicSharedMemorySize, FLASH_SMEM);
    flash_kernel<<<dim3(Sn / 64, Hn, Bn), 256, FLASH_SMEM>>>();

    // Output projection
    oproj_kernel<<<dim3(Bn * Sn / 64, 1, 1), 256>>>(WO, out);
}

// round 2
// speedup vs baseline: 5.9754x; 5.9754x over previous
#include <cuda_runtime.h>
#include <cstdint>

constexpr int Bn = 8, Sn = 2048, Dn = 512, Hn = 8;

// Device-global scratch
__device__ float g_Q[Bn * Hn * Sn * 64];   // [b,h,s,64]
__device__ float g_K[Bn * Hn * Sn * 64];
__device__ float g_V[Bn * Hn * Sn * 64];
__device__ float g_O[Bn * Sn * Hn * 64];   // [b,s, h*64]

__device__ __forceinline__ uint32_t f2tf(float x) {
    uint32_t r; asm("cvt.rna.tf32.f32 %0, %1;" : "=r"(r) : "f"(x)); return r;
}
__device__ __forceinline__ float ex2(float x) {
    float r; asm("ex2.approx.ftz.f32 %0, %1;" : "=f"(r) : "f"(x)); return r;
}
// D = A(16x8) * B(8x8) + D  row.col tf32
__device__ __forceinline__ void mma8(float* c, const uint32_t* a, const uint32_t* b) {
    asm volatile("mma.sync.aligned.m16n8k8.row.col.f32.tf32.tf32.f32 "
                 "{%0,%1,%2,%3},{%4,%5,%6,%7},{%8,%9},{%0,%1,%2,%3};"
                 : "+f"(c[0]), "+f"(c[1]), "+f"(c[2]), "+f"(c[3])
                 : "r"(a[0]), "r"(a[1]), "r"(a[2]), "r"(a[3]), "r"(b[0]), "r"(b[1]));
}

// ---------------------------------------------------------------------------
// Generic GEMM: C[128 x 64] = A[128 x 512] @ W[512 x 64]
// 128 threads, 4 warps; warp w owns rows 32w..32w+31.
// As ld=36 (conflict-free A-frag loads), Bs ld=72 (conflict-free B-frag loads)
// ---------------------------------------------------------------------------
__device__ __forceinline__ void gemm128x64(const float* __restrict__ A,
                                           const float* __restrict__ W,
                                           float* __restrict__ C)
{
    __shared__ uint32_t As[128 * 36];
    __shared__ uint32_t Bs[32 * 72];

    const int tid = threadIdx.x, w = tid >> 5, lane = tid & 31;
    const int gr = lane >> 2, tg = lane & 3;

    float c[2][8][4] = {};

    for (int kc = 0; kc < 512; kc += 32) {
        __syncthreads();
#pragma unroll
        for (int i = 0; i < 8; i++) {
            int g = tid + i * 128; int r = g >> 3, c4 = g & 7;
            float4 v = *reinterpret_cast<const float4*>(A + (size_t)r * 512 + kc + c4 * 4);
            uint32_t* d = &As[r * 36 + c4 * 4];
            d[0] = f2tf(v.x); d[1] = f2tf(v.y); d[2] = f2tf(v.z); d[3] = f2tf(v.w);
        }
#pragma unroll
        for (int i = 0; i < 4; i++) {
            int g = tid + i * 128; int r = g >> 4, c4 = g & 15;
            float4 v = *reinterpret_cast<const float4*>(W + (size_t)(kc + r) * 64 + c4 * 4);
            uint32_t* d = &Bs[r * 72 + c4 * 4];
            d[0] = f2tf(v.x); d[1] = f2tf(v.y); d[2] = f2tf(v.z); d[3] = f2tf(v.w);
        }
        __syncthreads();
#pragma unroll
        for (int ks = 0; ks < 4; ks++) {
            const int rb = 32 * w + gr, cA = ks * 8 + tg;
            uint32_t a0[4], a1[4];
            a0[0] = As[rb * 36 + cA];        a0[1] = As[(rb + 8) * 36 + cA];
            a0[2] = As[rb * 36 + cA + 4];    a0[3] = As[(rb + 8) * 36 + cA + 4];
            a1[0] = As[(rb + 16) * 36 + cA]; a1[1] = As[(rb + 24) * 36 + cA];
            a1[2] = As[(rb + 16) * 36 + cA + 4]; a1[3] = As[(rb + 24) * 36 + cA + 4];
#pragma unroll
            for (int nf = 0; nf < 8; nf++) {
                uint32_t b[2];
                b[0] = Bs[(ks * 8 + tg) * 72 + nf * 8 + gr];
                b[1] = Bs[(ks * 8 + tg + 4) * 72 + nf * 8 + gr];
                mma8(c[0][nf], a0, b);
                mma8(c[1][nf], a1, b);
            }
        }
    }
#pragma unroll
    for (int i = 0; i < 2; i++)
#pragma unroll
        for (int nf = 0; nf < 8; nf++) {
            int r = 32 * w + 16 * i + gr;
            int col = nf * 8 + 2 * tg;
            *reinterpret_cast<float2*>(C + (size_t)r * 64 + col) =
                make_float2(c[i][nf][0], c[i][nf][1]);
            *reinterpret_cast<float2*>(C + (size_t)(r + 8) * 64 + col) =
                make_float2(c[i][nf][2], c[i][nf][3]);
        }
}

// grid = (B*S/128, 24); z = which*8 + h
__global__ void __launch_bounds__(128) proj_kernel(const float* __restrict__ x,
                                                   const float* __restrict__ WQ,
                                                   const float* __restrict__ WK,
                                                   const float* __restrict__ WV)
{
    const int z = blockIdx.y;
    const int which = z >> 3, h = z & 7;
    const float* W = (which == 0) ? WQ : (which == 1) ? WK : WV;
    float* Og = (which == 0) ? g_Q : (which == 1) ? g_K : g_V;
    const int row0 = blockIdx.x * 128;
    const int b = row0 >> 11, s0 = row0 & 2047;
    gemm128x64(x + (size_t)row0 * 512, W + (size_t)h * 512 * 64,
               Og + ((size_t)(b * Hn + h) * Sn + s0) * 64);
}

__global__ void __launch_bounds__(128) oproj_kernel(const float* __restrict__ WO,
                                                    float* __restrict__ out)
{
    const int row0 = blockIdx.x * 128;
    gemm128x64(g_O + (size_t)row0 * 512, WO, out + (size_t)row0 * 64);
}

// ---------------------------------------------------------------------------
// Flash attention: grid = (S/128, H, B), 256 threads (8 warps, 16 q-rows each).
// O accumulator + softmax state in registers; P through smem (layout convert).
// smem: Ks[64*68], Vs[64*72], Ss[128*68] (tf32 bits)
// ---------------------------------------------------------------------------
__global__ void __launch_bounds__(256, 2) flash_kernel()
{
    extern __shared__ uint32_t smu[];
    uint32_t* Ks = smu;                 // 64*68 = 4352
    uint32_t* Vs = Ks + 64 * 68;        // 64*72 = 4608
    uint32_t* Ss = Vs + 64 * 72;        // 128*68 = 8704

    const int tid = threadIdx.x, w = tid >> 5, lane = tid & 31;
    const int gr = lane >> 2, tg = lane & 3;
    const int b = blockIdx.z, h = blockIdx.y, q0 = blockIdx.x * 128;

    const float* Qg = g_Q + ((size_t)(b * Hn + h) * Sn + q0) * 64;
    const float* Kg = g_K + (size_t)(b * Hn + h) * Sn * 64;
    const float* Vg = g_V + (size_t)(b * Hn + h) * Sn * 64;

    const int r = 16 * w + gr;   // this thread's first q-row (second is r+8)

    // Q fragments in registers, pre-scaled by 1/sqrt(64) * log2(e)
    const float qs = 0.125f * 1.44269504f;
    uint32_t qf[8][4];
#pragma unroll
    for (int ks = 0; ks < 8; ks++) {
        qf[ks][0] = f2tf(Qg[(size_t)r * 64 + ks * 8 + tg] * qs);
        qf[ks][1] = f2tf(Qg[(size_t)(r + 8) * 64 + ks * 8 + tg] * qs);
        qf[ks][2] = f2tf(Qg[(size_t)r * 64 + ks * 8 + tg + 4] * qs);
        qf[ks][3] = f2tf(Qg[(size_t)(r + 8) * 64 + ks * 8 + tg + 4] * qs);
    }

    float o[8][4] = {};
    float m0 = -1e30f, m1 = -1e30f, l0 = 0.0f, l1 = 0.0f;

    for (int j = 0; j < Sn; j += 64) {
        __syncthreads();
        // cooperative load of K,V tile (64x64 each), convert to tf32 at store
#pragma unroll
        for (int i = 0; i < 4; i++) {
            int g = tid + i * 256; int rr = g >> 4, c4 = g & 15;
            float4 kv = *reinterpret_cast<const float4*>(Kg + (size_t)(j + rr) * 64 + c4 * 4);
            uint32_t* dk = &Ks[rr * 68 + c4 * 4];
            dk[0] = f2tf(kv.x); dk[1] = f2tf(kv.y); dk[2] = f2tf(kv.z); dk[3] = f2tf(kv.w);
            float4 vv = *reinterpret_cast<const float4*>(Vg + (size_t)(j + rr) * 64 + c4 * 4);
            uint32_t* dv = &Vs[rr * 72 + c4 * 4];
            dv[0] = f2tf(vv.x); dv[1] = f2tf(vv.y); dv[2] = f2tf(vv.z); dv[3] = f2tf(vv.w);
        }
        __syncthreads();

        // S = Q @ K^T  (16 x 64 per warp)
        float s[8][4] = {};
#pragma unroll
        for (int ks = 0; ks < 8; ks++) {
#pragma unroll
            for (int nf = 0; nf < 8; nf++) {
                uint32_t bq[2];
                bq[0] = Ks[(nf * 8 + gr) * 68 + ks * 8 + tg];
                bq[1] = Ks[(nf * 8 + gr) * 68 + ks * 8 + tg + 4];
                mma8(s[nf], qf[ks], bq);
            }
        }

        // online softmax (log2 domain); rows r (c0,c1) and r+8 (c2,c3)
        float mx0 = -1e30f, mx1 = -1e30f;
#pragma unroll
        for (int nf = 0; nf < 8; nf++) {
            mx0 = fmaxf(mx0, fmaxf(s[nf][0], s[nf][1]));
            mx1 = fmaxf(mx1, fmaxf(s[nf][2], s[nf][3]));
        }
        mx0 = fmaxf(mx0, __shfl_xor_sync(0xffffffffu, mx0, 1));
        mx0 = fmaxf(mx0, __shfl_xor_sync(0xffffffffu, mx0, 2));
        mx1 = fmaxf(mx1, __shfl_xor_sync(0xffffffffu, mx1, 1));
        mx1 = fmaxf(mx1, __shfl_xor_sync(0xffffffffu, mx1, 2));
        const float mn0 = fmaxf(m0, mx0), mn1 = fmaxf(m1, mx1);
        const float al0 = ex2(m0 - mn0),  al1 = ex2(m1 - mn1);
        m0 = mn0; m1 = mn1;

        float ps0 = 0.0f, ps1 = 0.0f;
        const int rs = 16 * w + gr;
#pragma unroll
        for (int nf = 0; nf < 8; nf++) {
            float p0 = ex2(s[nf][0] - mn0), p1 = ex2(s[nf][1] - mn0);
            float p2 = ex2(s[nf][2] - mn1), p3 = ex2(s[nf][3] - mn1);
            ps0 += p0 + p1; ps1 += p2 + p3;
            const int col = nf * 8 + 2 * tg;
            Ss[rs * 68 + col]           = f2tf(p0);
            Ss[rs * 68 + col + 1]       = f2tf(p1);
            Ss[(rs + 8) * 68 + col]     = f2tf(p2);
            Ss[(rs + 8) * 68 + col + 1] = f2tf(p3);
            o[nf][0] *= al0; o[nf][1] *= al0;
            o[nf][2] *= al1; o[nf][3] *= al1;
        }
        ps0 += __shfl_xor_sync(0xffffffffu, ps0, 1);
        ps0 += __shfl_xor_sync(0xffffffffu, ps0, 2);
        ps1 += __shfl_xor_sync(0xffffffffu, ps1, 1);
        ps1 += __shfl_xor_sync(0xffffffffu, ps1, 2);
        l0 = l0 * al0 + ps0;
        l1 = l1 * al1 + ps1;
        __syncwarp();

        // O += P @ V
#pragma unroll
        for (int ks = 0; ks < 8; ks++) {
            uint32_t pa[4];
            const int pc = ks * 8 + tg;
            pa[0] = Ss[rs * 68 + pc];       pa[1] = Ss[(rs + 8) * 68 + pc];
            pa[2] = Ss[rs * 68 + pc + 4];   pa[3] = Ss[(rs + 8) * 68 + pc + 4];
#pragma unroll
            for (int nf = 0; nf < 8; nf++) {
                uint32_t bv[2];
                bv[0] = Vs[(ks * 8 + tg) * 72 + nf * 8 + gr];
                bv[1] = Vs[(ks * 8 + tg + 4) * 72 + nf * 8 + gr];
                mma8(o[nf], pa, bv);
            }
        }
    }

    // finalize: divide by l, write to concat layout [b, s, h*64 + col]
    const float i0 = 1.0f / l0, i1 = 1.0f / l1;
    float* Og = g_O + (size_t)(b * Sn + q0 + r) * (Hn * 64) + h * 64;
#pragma unroll
    for (int nf = 0; nf < 8; nf++) {
        const int col = nf * 8 + 2 * tg;
        *reinterpret_cast<float2*>(Og + col) =
            make_float2(o[nf][0] * i0, o[nf][1] * i0);
        *reinterpret_cast<float2*>(Og + 8 * (Hn * 64) + col) =
            make_float2(o[nf][2] * i1, o[nf][3] * i1);
    }
}

// ---------------------------------------------------------------------------
extern "C" void kernel_launch(void* const* d_in, const int* in_sizes, int n_in,
                              void* d_out, int out_size)
{
    const float* x  = (const float*)d_in[0];
    const float* WQ = (const float*)d_in[1];
    const float* WK = (const float*)d_in[2];
    const float* WV = (const float*)d_in[3];
    const float* WO = (const float*)d_in[4];
    float* out = (float*)d_out;

    proj_kernel<<<dim3(Bn * Sn / 128, 24), 128>>>(x, WQ, WK, WV);

    constexpr int FLASH_SMEM = (64 * 68 + 64 * 72 + 128 * 68) * (int)sizeof(uint32_t); // 70656
    cudaFuncSetAttribute(flash_kernel, cudaFuncAttributeMaxDynamicSharedMemorySize, FLASH_SMEM);
    flash_kernel<<<dim3(Sn / 128, Hn, Bn), 256, FLASH_SMEM>>>();

    oproj_kernel<<<dim3(Bn * Sn / 128, 1, 1), 128>>>(WO, out);
}